// round 6
// baseline (speedup 1.0000x reference)
#include <cuda_runtime.h>
#include <cuda_bf16.h>

// Shapes (fixed by problem): B=16, R=64, NOBJ=32, SIZE=64, N=B*R=1024
// Pipeline per pair: rect masks (2x64x64) -> conv1 5x5 (64ch) -> pool2 ->
//  conv2 5x5 (32ch) -> pool2 -> mean -> fc(32->512) -> relu
// conv1 computed analytically (rect indicator is separable); conv2 fused on
// SMEM-resident x1 (64x30x30) with packed f32x2 FMAs, 6 pooled positions
// resident per thread so each conv2 weight is loaded exactly once per thread.

typedef unsigned long long ull;

// Re-laid-out conv2 weights: g_wT[k*32 + o], k = c*25 + p*5 + q  (k-major)
__device__ __align__(16) float g_wT[1600 * 32];
// Column prefix of conv1 weights: g_cp[(o*2+c)*30 + p*5 + q] = sum_{p'<p} w1[o,c,p',q]
__device__ float g_cp[64 * 2 * 30];

__device__ __forceinline__ ull pk2(float a, float b) {
    ull r; asm("mov.b64 %0, {%1,%2};" : "=l"(r) : "f"(a), "f"(b)); return r;
}
__device__ __forceinline__ void upk2(float& a, float& b, ull v) {
    asm("mov.b64 {%0,%1}, %2;" : "=f"(a), "=f"(b) : "l"(v));
}
__device__ __forceinline__ void ffma2(ull& d, ull a, ull b) {
    asm("fma.rn.f32x2 %0, %1, %2, %0;" : "+l"(d) : "l"(a), "l"(b));
}

__global__ void setup_kernel(const float* __restrict__ w1,
                             const float* __restrict__ w2) {
    int tid = blockIdx.x * blockDim.x + threadIdx.x;
    if (tid < 128) {
        int o = tid >> 1, c = tid & 1;
        const float* w = w1 + (o * 2 + c) * 25;
        float* dst = g_cp + (o * 2 + c) * 30;
        float acc[5] = {0.f, 0.f, 0.f, 0.f, 0.f};
        #pragma unroll
        for (int q = 0; q < 5; q++) dst[q] = 0.f;
        for (int p = 1; p < 6; p++) {
            #pragma unroll
            for (int q = 0; q < 5; q++) {
                acc[q] += w[(p - 1) * 5 + q];
                dst[p * 5 + q] = acc[q];
            }
        }
    }
    for (int idx = tid; idx < 1600 * 32; idx += blockDim.x * gridDim.x) {
        int k = idx >> 5, o = idx & 31;
        g_wT[idx] = w2[o * 1600 + k];
    }
}

// SMEM layout (floats): x1[57600] | feat[32] | part[32]
#define X1_FLOATS 57600
#define SMEM_FLOATS (X1_FLOATS + 32 + 32)

__global__ __launch_bounds__(256, 1) void spatial_kernel(
    const float* __restrict__ bboxes,   // [B][NOBJ][4]
    const int*   __restrict__ pairs,    // [B][R][2]
    const float* __restrict__ b1,       // [64]
    const float* __restrict__ b2,       // [32]
    const float* __restrict__ fcw,      // [512][32]
    const float* __restrict__ fcb,      // [512]
    float*       __restrict__ out,      // [N][512]
    int R, int NOBJ)
{
    extern __shared__ float smem[];
    float* x1   = smem;
    float* feat = smem + X1_FLOATS;
    float* part = smem + X1_FLOATS + 32;

    const int n   = blockIdx.x;
    const int b   = n / R;
    const int tid = threadIdx.x;

    // ---------- Phase A: rectangle bounds (redundant per thread, cheap) ----
    int pi0 = pairs[n * 2 + 0];
    int pi1 = pairs[n * 2 + 1];
    float4 bb0 = *(const float4*)(bboxes + (b * NOBJ + pi0) * 4);
    float4 bb1 = *(const float4*)(bboxes + (b * NOBJ + pi1) * 4);
    float ux1 = fminf(bb0.x, bb1.x), uy1 = fminf(bb0.y, bb1.y);
    float ux2 = fmaxf(bb0.z, bb1.z), uy2 = fmaxf(bb0.w, bb1.w);
    float uw = fmaxf(ux2 - ux1, 1e-6f), uh = fmaxf(uy2 - uy1, 1e-6f);

    float sx1c[2], sx2c[2], sy1c[2], sy2c[2];
    sx1c[0] = (bb0.x - ux1) / uw * 64.f;  sy1c[0] = (bb0.y - uy1) / uh * 64.f;
    sx2c[0] = (bb0.z - ux1) / uw * 64.f;  sy2c[0] = (bb0.w - uy1) / uh * 64.f;
    sx1c[1] = (bb1.x - ux1) / uw * 64.f;  sy1c[1] = (bb1.y - uy1) / uh * 64.f;
    sx2c[1] = (bb1.z - ux1) / uw * 64.f;  sy2c[1] = (bb1.w - uy1) / uh * 64.f;

    // Exact integer bounds via scan (matches reference float comparisons
    // bit-for-bit; analytic ceil/floor could flip boundary ties).
    int cxlo[2], cxhi[2], rylo[2], ryhi[2];
    #pragma unroll
    for (int c = 0; c < 2; c++) {
        int lo = 64, hi = -1;
        for (int j = 0; j < 64; j++) {
            float g = (float)j + 0.5f;
            if (g >= sx1c[c] && g <= sx2c[c]) { if (j < lo) lo = j; hi = j; }
        }
        cxlo[c] = lo; cxhi[c] = hi;
        lo = 64; hi = -1;
        for (int j = 0; j < 64; j++) {
            float g = (float)j + 0.5f;
            if (g >= sy1c[c] && g <= sy2c[c]) { if (j < lo) lo = j; hi = j; }
        }
        rylo[c] = lo; ryhi[c] = hi;
    }

    // ---------- Phase C: analytic conv1 (+bias) + pool1 -> x1 in SMEM -----
    {
        int o = tid & 63;
        float bias1 = b1[o];
        const float* cpb[2] = { g_cp + (o * 2 + 0) * 30, g_cp + (o * 2 + 1) * 30 };
        for (int I = tid >> 6; I < 30; I += 4) {
            float rw[2][2][5];  // [row-within-pool rr][in-ch c][q]
            #pragma unroll
            for (int rr = 0; rr < 2; rr++) {
                int i = 2 * I + rr;
                #pragma unroll
                for (int c = 0; c < 2; c++) {
                    const float* cp = cpb[c];
                    int pl = max(0, rylo[c] - i);
                    int ph = min(4, ryhi[c] - i);
                    if (ph >= pl) {
                        #pragma unroll
                        for (int q = 0; q < 5; q++)
                            rw[rr][c][q] = cp[(ph + 1) * 5 + q] - cp[pl * 5 + q];
                    } else {
                        #pragma unroll
                        for (int q = 0; q < 5; q++) rw[rr][c][q] = 0.f;
                    }
                }
            }
            float* dst = x1 + o * 900 + I * 30;
            for (int J = 0; J < 30; J++) {
                int j0 = 2 * J;
                float v00 = 0.f, v01 = 0.f, v10 = 0.f, v11 = 0.f;
                #pragma unroll
                for (int c = 0; c < 2; c++) {
                    #pragma unroll
                    for (int q = 0; q < 5; q++) {
                        bool u0 = (j0 + q)     >= cxlo[c] && (j0 + q)     <= cxhi[c];
                        bool u1 = (j0 + 1 + q) >= cxlo[c] && (j0 + 1 + q) <= cxhi[c];
                        v00 += u0 ? rw[0][c][q] : 0.f;
                        v10 += u0 ? rw[1][c][q] : 0.f;
                        v01 += u1 ? rw[0][c][q] : 0.f;
                        v11 += u1 ? rw[1][c][q] : 0.f;
                    }
                }
                dst[J] = fmaxf(fmaxf(v00, v01), fmaxf(v10, v11)) + bias1;
            }
        }
    }
    __syncthreads();

    // ---------- Phase D: conv2 + pool2 + mean (f32x2, 6 resident pos) -----
    const int warp  = tid >> 5;
    const int lane  = tid & 31;
    const int obase = warp * 4;           // each warp owns 4 output channels

    int   boff[6];
    float vmask[6];
    #pragma unroll
    for (int r = 0; r < 6; r++) {
        int pp = lane + 32 * r;           // pooled position 0..191 (169 valid)
        vmask[r] = (pp < 169) ? 1.f : 0.f;
        int ppc = min(pp, 168);
        int Ip = ppc / 13, Jp = ppc - Ip * 13;
        boff[r] = Ip * 60 + Jp * 2;       // x1 patch base (row 2Ip, col 2Jp)
    }

    ull acc[6][4][2];                     // [pos][di*2+dj][o-pair]
    #pragma unroll
    for (int r = 0; r < 6; r++)
        #pragma unroll
        for (int w4 = 0; w4 < 4; w4++) { acc[r][w4][0] = 0ull; acc[r][w4][1] = 0ull; }

    const float* wgbase = g_wT + obase;

    // unroll 2: lets ptxas hoist channel c+1's weight LDGs into channel c's
    // FMA stream (cross-channel software pipelining; ~220 live regs, no spill).
    #pragma unroll 2
    for (int c = 0; c < 64; c++) {
        const float* xc = x1 + c * 900;
        const float* wc = wgbase + c * 800;   // 25*32 floats per input channel
        ull wrow[5][2], wprev[5][2];
        #pragma unroll
        for (int u = 0; u < 6; u++) {
            if (u < 5) {
                #pragma unroll
                for (int q = 0; q < 5; q++) {
                    float4 wv = *(const float4*)(wc + (u * 5 + q) * 32);
                    wrow[q][0] = pk2(wv.x, wv.y);
                    wrow[q][1] = pk2(wv.z, wv.w);
                }
            }
            #pragma unroll
            for (int r = 0; r < 6; r++) {
                const float* xr = xc + boff[r] + u * 30;   // 8B-aligned
                float2 f01 = *(const float2*)(xr);
                float2 f23 = *(const float2*)(xr + 2);
                float2 f45 = *(const float2*)(xr + 4);
                ull xx[6];
                xx[0] = pk2(f01.x, f01.x); xx[1] = pk2(f01.y, f01.y);
                xx[2] = pk2(f23.x, f23.x); xx[3] = pk2(f23.y, f23.y);
                xx[4] = pk2(f45.x, f45.x); xx[5] = pk2(f45.y, f45.y);
                if (u <= 4) {                               // di=0 uses row u
                    #pragma unroll
                    for (int dj = 0; dj < 2; dj++)
                        #pragma unroll
                        for (int q = 0; q < 5; q++) {
                            ffma2(acc[r][dj][0], xx[dj + q], wrow[q][0]);
                            ffma2(acc[r][dj][1], xx[dj + q], wrow[q][1]);
                        }
                }
                if (u >= 1) {                               // di=1 uses row u-1
                    #pragma unroll
                    for (int dj = 0; dj < 2; dj++)
                        #pragma unroll
                        for (int q = 0; q < 5; q++) {
                            ffma2(acc[r][2 + dj][0], xx[dj + q], wprev[q][0]);
                            ffma2(acc[r][2 + dj][1], xx[dj + q], wprev[q][1]);
                        }
                }
            }
            #pragma unroll
            for (int q = 0; q < 5; q++) {     // rotate (register-renamed)
                wprev[q][0] = wrow[q][0];
                wprev[q][1] = wrow[q][1];
            }
        }
    }

    // 2x2 maxpool per output channel, accumulate spatial mean over positions
    float lsum[4] = {0.f, 0.f, 0.f, 0.f};
    #pragma unroll
    for (int r = 0; r < 6; r++) {
        #pragma unroll
        for (int pr = 0; pr < 2; pr++) {
            float a0, b0v, a1, b1v, a2, b2v, a3, b3v;
            upk2(a0, b0v, acc[r][0][pr]);
            upk2(a1, b1v, acc[r][1][pr]);
            upk2(a2, b2v, acc[r][2][pr]);
            upk2(a3, b3v, acc[r][3][pr]);
            lsum[pr * 2 + 0] += vmask[r] * fmaxf(fmaxf(a0, a1), fmaxf(a2, a3));
            lsum[pr * 2 + 1] += vmask[r] * fmaxf(fmaxf(b0v, b1v), fmaxf(b2v, b3v));
        }
    }

    // ---------- Phase E: reduce to feat[32], then fc + relu ----------------
    #pragma unroll
    for (int m = 0; m < 4; m++) {
        float v = lsum[m];
        v += __shfl_xor_sync(0xFFFFFFFFu, v, 16);
        v += __shfl_xor_sync(0xFFFFFFFFu, v, 8);
        v += __shfl_xor_sync(0xFFFFFFFFu, v, 4);
        v += __shfl_xor_sync(0xFFFFFFFFu, v, 2);
        v += __shfl_xor_sync(0xFFFFFFFFu, v, 1);
        lsum[m] = v;
    }
    if (lane == 0) {
        #pragma unroll
        for (int m = 0; m < 4; m++) part[obase + m] = lsum[m];
    }
    __syncthreads();
    if (tid < 32) {
        feat[tid] = part[tid] * (1.f / 169.f) + b2[tid];
    }
    __syncthreads();

    #pragma unroll
    for (int t0 = 0; t0 < 2; t0++) {
        int t = tid + t0 * 256;
        float facc = fcb[t];
        const float4* wrow2 = (const float4*)(fcw + t * 32);
        #pragma unroll
        for (int k4 = 0; k4 < 8; k4++) {
            float4 w = wrow2[k4];
            facc += feat[k4 * 4 + 0] * w.x + feat[k4 * 4 + 1] * w.y
                  + feat[k4 * 4 + 2] * w.z + feat[k4 * 4 + 3] * w.w;
        }
        out[(size_t)n * 512 + t] = fmaxf(facc, 0.f);
    }
}

extern "C" void kernel_launch(void* const* d_in, const int* in_sizes, int n_in,
                              void* d_out, int out_size) {
    const float* bboxes = (const float*)d_in[0];
    // d_in[1] num_obj, d_in[2] num_relation: unused by reference math
    const int*   pairs  = (const int*)  d_in[3];
    const float* w1     = (const float*)d_in[4];
    const float* b1     = (const float*)d_in[5];
    const float* w2     = (const float*)d_in[6];
    const float* b2     = (const float*)d_in[7];
    const float* fcw    = (const float*)d_in[8];
    const float* fcb    = (const float*)d_in[9];
    float* out = (float*)d_out;

    int N = in_sizes[3] / 2;          // B*R pairs
    int B = in_sizes[1];              // num_obj has B entries
    int R = N / B;
    int NOBJ = in_sizes[0] / (4 * B);

    setup_kernel<<<208, 256>>>(w1, w2);

    int smem_bytes = SMEM_FLOATS * (int)sizeof(float);
    cudaFuncSetAttribute(spatial_kernel,
                         cudaFuncAttributeMaxDynamicSharedMemorySize, smem_bytes);
    spatial_kernel<<<N, 256, smem_bytes>>>(bboxes, pairs, b1, b2, fcw, fcb,
                                           out, R, NOBJ);
}